// round 7
// baseline (speedup 1.0000x reference)
#include <cuda_runtime.h>
#include <stdint.h>

// FloodPath: 16-step binary flood fill, bit-packed, ONE persistent kernel.
// Warp = one row (lane holds 4 consecutive words). All state (free, flood,
// 5 count bit-planes) lives in registers. Vertical neighbors: smem within
// CTA, parity-buffered global edge rows + flag handshake between CTAs.

#define HW    4096
#define WPR   128        // words per row
#define STEPS 16
#define NCTA  128
#define RPC   32         // rows per CTA (= warps per CTA)
#define NT    1024

__device__ uint32_t g_edge_top[2][NCTA][WPR]; // CTA's top row (plane t-1)
__device__ uint32_t g_edge_bot[2][NCTA][WPR]; // CTA's bottom row
__device__ volatile int g_flag_top[NCTA];     // last step posted
__device__ volatile int g_flag_bot[NCTA];

__global__ void init_kernel()
{
    int i = threadIdx.x;
    if (i < NCTA) { g_flag_top[i] = 0; g_flag_bot[i] = 0; }
}

__global__ void __launch_bounds__(NT)
flood_kernel(const float2* __restrict__ in, float* __restrict__ out)
{
    __shared__ uint32_t buf[2][RPC][WPR];     // row plane, parity buffered

    const int tid  = threadIdx.x;
    const int warp = tid >> 5;
    const int lane = tid & 31;
    const int cb   = blockIdx.x;
    const int y    = cb * RPC + warp;         // row owned by this warp
    // lane owns words lane*4 .. lane*4+3 of its row (component j)

    // ---- pack: ballot 32 cells -> word; keep when this lane owns the word
    uint32_t fr[4], s[4];
    const float2* rowp = in + (size_t)y * HW;
#pragma unroll
    for (int j = 0; j < 4; j++) {
        uint32_t frw = 0u, sw = 0u;
#pragma unroll 8
        for (int ow = 0; ow < 32; ow++) {
            const int i = ow * 4 + j;                    // word in row
            float2 v = rowp[i * 32 + lane];
            uint32_t bf = __ballot_sync(0xffffffffu, v.x == 0.f);
            uint32_t bl = __ballot_sync(0xffffffffu, v.y != 0.f);
            if (lane == ow) { frw = bf; sw = bl; }
        }
        fr[j] = frw; s[j] = sw;
    }

    uint32_t c0[4] = {0,0,0,0}, c1[4] = {0,0,0,0}, c2[4] = {0,0,0,0},
             c3[4] = {0,0,0,0}, c4[4] = {0,0,0,0};

    // ---- 16 steps, all state in registers
#pragma unroll 1
    for (int t = 1; t <= STEPS; t++) {
        const int par = t & 1;

        // post boundary rows (plane t-1) to neighbors, then signal
        if (warp == 0) {
            *(uint4*)&g_edge_top[par][cb][lane * 4] =
                make_uint4(s[0], s[1], s[2], s[3]);
            __threadfence();
            __syncwarp();
            if (lane == 0) g_flag_top[cb] = t;
        }
        if (warp == RPC - 1) {
            *(uint4*)&g_edge_bot[par][cb][lane * 4] =
                make_uint4(s[0], s[1], s[2], s[3]);
            __threadfence();
            __syncwarp();
            if (lane == 0) g_flag_bot[cb] = t;
        }

        // share rows within CTA
        *(uint4*)&buf[par][warp][lane * 4] = make_uint4(s[0], s[1], s[2], s[3]);
        __syncthreads();

        uint4 up, dn;
        if (warp > 0) {
            up = *(const uint4*)&buf[par][warp - 1][lane * 4];
        } else if (cb > 0) {
            while (g_flag_bot[cb - 1] < t) { }
            __threadfence();
            up = *(const uint4*)&g_edge_bot[par][cb - 1][lane * 4];
        } else {
            up = make_uint4(0u, 0u, 0u, 0u);
        }
        if (warp < RPC - 1) {
            dn = *(const uint4*)&buf[par][warp + 1][lane * 4];
        } else if (cb < NCTA - 1) {
            while (g_flag_top[cb + 1] < t) { }
            __threadfence();
            dn = *(const uint4*)&g_edge_top[par][cb + 1][lane * 4];
        } else {
            dn = make_uint4(0u, 0u, 0u, 0u);
        }

        uint32_t lf = __shfl_up_sync(0xffffffffu, s[3], 1);
        uint32_t rt = __shfl_down_sync(0xffffffffu, s[0], 1);
        if (lane == 0)  lf = 0u;
        if (lane == 31) rt = 0u;

        uint32_t n0 = (s[0] | up.x | dn.x | __funnelshift_l(lf,   s[0], 1)
                                          | __funnelshift_r(s[0], s[1], 1)) & fr[0];
        uint32_t n1 = (s[1] | up.y | dn.y | __funnelshift_l(s[0], s[1], 1)
                                          | __funnelshift_r(s[1], s[2], 1)) & fr[1];
        uint32_t n2 = (s[2] | up.z | dn.z | __funnelshift_l(s[1], s[2], 1)
                                          | __funnelshift_r(s[2], s[3], 1)) & fr[2];
        uint32_t n3 = (s[3] | up.w | dn.w | __funnelshift_l(s[2], s[3], 1)
                                          | __funnelshift_r(s[3], rt,   1)) & fr[3];
        s[0] = n0; s[1] = n1; s[2] = n2; s[3] = n3;

        // count += flood  (bit-plane ripple adder, in registers)
#pragma unroll
        for (int j = 0; j < 4; j++) {
            uint32_t carry = s[j], x;
            x = c0[j] & carry; c0[j] ^= carry; carry = x;
            x = c1[j] & carry; c1[j] ^= carry; carry = x;
            x = c2[j] & carry; c2[j] ^= carry; carry = x;
            x = c3[j] & carry; c3[j] ^= carry; carry = x;
            c4[j] ^= carry;
        }
    }

    // ---- unpack: shfl-broadcast each word's registers; lane = cell bit.
    const size_t rowbase = (size_t)y * HW * 3;
#pragma unroll
    for (int j = 0; j < 4; j++) {
#pragma unroll 4
        for (int ow = 0; ow < 32; ow++) {
            const uint32_t bfr = __shfl_sync(0xffffffffu, fr[j], ow);
            const uint32_t bs  = __shfl_sync(0xffffffffu, s[j],  ow);
            const uint32_t b0  = __shfl_sync(0xffffffffu, c0[j], ow);
            const uint32_t b1  = __shfl_sync(0xffffffffu, c1[j], ow);
            const uint32_t b2  = __shfl_sync(0xffffffffu, c2[j], ow);
            const uint32_t b3  = __shfl_sync(0xffffffffu, c3[j], ow);
            const uint32_t b4  = __shfl_sync(0xffffffffu, c4[j], ow);

            const int k = ow * 4 + j;                    // word in row
            float* o = out + rowbase + (size_t)k * 96 + lane * 3;
            o[0] = ((bfr >> lane) & 1u) ? 0.0f : 1.0f;   // occupied
            o[1] = ((bs  >> lane) & 1u) ? 1.0f : 0.0f;   // flood
            const uint32_t cc =  ((b0 >> lane) & 1u)
                              | (((b1 >> lane) & 1u) << 1)
                              | (((b2 >> lane) & 1u) << 2)
                              | (((b3 >> lane) & 1u) << 3)
                              | (((b4 >> lane) & 1u) << 4);
            o[2] = (float)cc;                            // count 0..16
        }
    }
}

extern "C" void kernel_launch(void* const* d_in, const int* in_sizes, int n_in,
                              void* d_out, int out_size)
{
    const float2* in  = (const float2*)d_in[0];  // flood_input [H,W,2] f32
    float*        out = (float*)d_out;           // [H,W,3] f32
    (void)in_sizes; (void)n_in; (void)out_size;

    init_kernel<<<1, 128>>>();                   // reset handshake flags
    flood_kernel<<<NCTA, NT>>>(in, out);         // persistent, single wave
}

// round 9
// speedup vs baseline: 1.6846x; 1.6846x over previous
#include <cuda_runtime.h>
#include <stdint.h>

// FloodPath: 16-step binary flood fill, bit-packed.
// R9 (= R8 resubmit): R6's coalesced pack/unpack kernels + ONE persistent
// step kernel (warp = row, lane = 4 words, 16 steps in registers, smem +
// flag handshake for vertical exchange, count bit-planes in registers).

#define HW    4096
#define WPR   128                 // 32-bit words per row
#define NWORD (HW * WPR)          // 524288 words = 2 MB per plane
#define STEPS 16
#define NCTA  128
#define RPC   32                  // rows per CTA (= warps)
#define NT    1024

__device__ uint32_t g_free[NWORD];            // bit=1: cell is free
__device__ uint32_t g_fld0[NWORD];            // initial flood
__device__ uint32_t g_fld[NWORD];             // final flood
__device__ uint32_t g_cnt[5][NWORD];          // count bit-planes

__device__ uint32_t g_edge_top[2][NCTA][WPR]; // CTA's top row (plane t-1)
__device__ uint32_t g_edge_bot[2][NCTA][WPR]; // CTA's bottom row
__device__ volatile int g_flag_top[NCTA];     // last step posted
__device__ volatile int g_flag_bot[NCTA];

__global__ void init_kernel()
{
    int i = threadIdx.x;
    if (i < NCTA) { g_flag_top[i] = 0; g_flag_bot[i] = 0; }
}

// ---- pack: warp ballots 32 cells -> 1 word. Coalesced 256B loads.
__global__ void __launch_bounds__(256)
pack_kernel(const float2* __restrict__ in)
{
    const int warp = (blockIdx.x * 256 + threadIdx.x) >> 5;
    const int lane = threadIdx.x & 31;
    const int w0   = warp * 32;
#pragma unroll 4
    for (int i = 0; i < 32; i++) {
        int w = w0 + i;
        float2 v = in[(size_t)w * 32 + lane];
        uint32_t fr = __ballot_sync(0xffffffffu, v.x == 0.f);
        uint32_t fl = __ballot_sync(0xffffffffu, v.y != 0.f);
        if (lane == 0) { g_free[w] = fr; g_fld0[w] = fl; }
    }
}

// ---- all 16 steps in one persistent kernel. Warp = row; lane owns words
// lane*4..lane*4+3. Single wave (128 CTAs < 148 SMs), flag handshake
// across CTAs (monotonic per-launch step counters, reset by init_kernel).
__global__ void __launch_bounds__(NT)
step16_kernel()
{
    __shared__ uint32_t buf[2][RPC][WPR];     // row plane, parity buffered

    const int tid  = threadIdx.x;
    const int warp = tid >> 5;
    const int lane = tid & 31;
    const int cb   = blockIdx.x;
    const int y    = cb * RPC + warp;
    const int b    = y * WPR + lane * 4;

    uint4 frv = *(const uint4*)(g_free + b);
    uint4 sv  = *(const uint4*)(g_fld0 + b);
    uint32_t fr[4] = {frv.x, frv.y, frv.z, frv.w};
    uint32_t s[4]  = {sv.x,  sv.y,  sv.z,  sv.w};

    uint32_t c0[4] = {0,0,0,0}, c1[4] = {0,0,0,0}, c2[4] = {0,0,0,0},
             c3[4] = {0,0,0,0}, c4[4] = {0,0,0,0};

#pragma unroll 1
    for (int t = 1; t <= STEPS; t++) {
        const int par = t & 1;

        // post boundary rows (plane t-1) to neighbor CTAs, then signal
        if (warp == 0) {
            *(uint4*)&g_edge_top[par][cb][lane * 4] =
                make_uint4(s[0], s[1], s[2], s[3]);
            __threadfence();
            __syncwarp();
            if (lane == 0) g_flag_top[cb] = t;
        }
        if (warp == RPC - 1) {
            *(uint4*)&g_edge_bot[par][cb][lane * 4] =
                make_uint4(s[0], s[1], s[2], s[3]);
            __threadfence();
            __syncwarp();
            if (lane == 0) g_flag_bot[cb] = t;
        }

        // share rows within CTA
        *(uint4*)&buf[par][warp][lane * 4] = make_uint4(s[0], s[1], s[2], s[3]);
        __syncthreads();

        uint4 up, dn;
        if (warp > 0) {
            up = *(const uint4*)&buf[par][warp - 1][lane * 4];
        } else if (cb > 0) {
            while (g_flag_bot[cb - 1] < t) { __nanosleep(32); }
            __threadfence();
            up = *(const uint4*)&g_edge_bot[par][cb - 1][lane * 4];
        } else {
            up = make_uint4(0u, 0u, 0u, 0u);
        }
        if (warp < RPC - 1) {
            dn = *(const uint4*)&buf[par][warp + 1][lane * 4];
        } else if (cb < NCTA - 1) {
            while (g_flag_top[cb + 1] < t) { __nanosleep(32); }
            __threadfence();
            dn = *(const uint4*)&g_edge_top[par][cb + 1][lane * 4];
        } else {
            dn = make_uint4(0u, 0u, 0u, 0u);
        }

        uint32_t lf = __shfl_up_sync(0xffffffffu, s[3], 1);
        uint32_t rt = __shfl_down_sync(0xffffffffu, s[0], 1);
        if (lane == 0)  lf = 0u;
        if (lane == 31) rt = 0u;

        uint32_t n0 = (s[0] | up.x | dn.x | __funnelshift_l(lf,   s[0], 1)
                                          | __funnelshift_r(s[0], s[1], 1)) & fr[0];
        uint32_t n1 = (s[1] | up.y | dn.y | __funnelshift_l(s[0], s[1], 1)
                                          | __funnelshift_r(s[1], s[2], 1)) & fr[1];
        uint32_t n2 = (s[2] | up.z | dn.z | __funnelshift_l(s[1], s[2], 1)
                                          | __funnelshift_r(s[2], s[3], 1)) & fr[2];
        uint32_t n3 = (s[3] | up.w | dn.w | __funnelshift_l(s[2], s[3], 1)
                                          | __funnelshift_r(s[3], rt,   1)) & fr[3];
        s[0] = n0; s[1] = n1; s[2] = n2; s[3] = n3;

#pragma unroll
        for (int j = 0; j < 4; j++) {
            uint32_t carry = s[j], x;
            x = c0[j] & carry; c0[j] ^= carry; carry = x;
            x = c1[j] & carry; c1[j] ^= carry; carry = x;
            x = c2[j] & carry; c2[j] ^= carry; carry = x;
            x = c3[j] & carry; c3[j] ^= carry; carry = x;
            c4[j] ^= carry;
        }
    }

    // write results (coalesced uint4)
    *(uint4*)(g_fld    + b) = make_uint4(s[0],  s[1],  s[2],  s[3]);
    *(uint4*)(g_cnt[0] + b) = make_uint4(c0[0], c0[1], c0[2], c0[3]);
    *(uint4*)(g_cnt[1] + b) = make_uint4(c1[0], c1[1], c1[2], c1[3]);
    *(uint4*)(g_cnt[2] + b) = make_uint4(c2[0], c2[1], c2[2], c2[3]);
    *(uint4*)(g_cnt[3] + b) = make_uint4(c3[0], c3[1], c3[2], c3[3]);
    *(uint4*)(g_cnt[4] + b) = make_uint4(c4[0], c4[1], c4[2], c4[3]);
}

// ---- unpack: lane owns word w0+lane (coalesced loads), shfl-broadcast each
// word's 7 values; lane = cell bit, coalesced 384B span per word.
__global__ void __launch_bounds__(256)
unpack_kernel(float* __restrict__ out)
{
    const int w    = blockIdx.x * 256 + threadIdx.x;
    const int lane = threadIdx.x & 31;
    const int w0   = w - lane;

    const uint32_t fr = g_free[w];
    const uint32_t fw = g_fld[w];
    const uint32_t c0 = g_cnt[0][w];
    const uint32_t c1 = g_cnt[1][w];
    const uint32_t c2 = g_cnt[2][w];
    const uint32_t c3 = g_cnt[3][w];
    const uint32_t c4 = g_cnt[4][w];

#pragma unroll
    for (int k = 0; k < 32; k++) {
        const uint32_t bfr = __shfl_sync(0xffffffffu, fr, k);
        const uint32_t bfw = __shfl_sync(0xffffffffu, fw, k);
        const uint32_t b0  = __shfl_sync(0xffffffffu, c0, k);
        const uint32_t b1  = __shfl_sync(0xffffffffu, c1, k);
        const uint32_t b2  = __shfl_sync(0xffffffffu, c2, k);
        const uint32_t b3  = __shfl_sync(0xffffffffu, c3, k);
        const uint32_t b4  = __shfl_sync(0xffffffffu, c4, k);

        const float occ = (float)(((bfr >> lane) & 1u) ^ 1u);
        const float fld = (float)((bfw >> lane) & 1u);
        const uint32_t c =  ((b0 >> lane) & 1u)
                         | (((b1 >> lane) & 1u) << 1)
                         | (((b2 >> lane) & 1u) << 2)
                         | (((b3 >> lane) & 1u) << 3)
                         | (((b4 >> lane) & 1u) << 4);

        float* o = out + (size_t)(w0 + k) * 96 + lane * 3;
        o[0] = occ;
        o[1] = fld;
        o[2] = (float)c;
    }
}

extern "C" void kernel_launch(void* const* d_in, const int* in_sizes, int n_in,
                              void* d_out, int out_size)
{
    const float2* in  = (const float2*)d_in[0];  // flood_input [H,W,2] f32
    float*        out = (float*)d_out;           // [H,W,3] f32
    (void)in_sizes; (void)n_in; (void)out_size;

    init_kernel<<<1, 128>>>();                   // reset handshake flags
    pack_kernel<<<2048, 256>>>(in);
    step16_kernel<<<NCTA, NT>>>();               // persistent, single wave
    unpack_kernel<<<2048, 256>>>(out);
}

// round 10
// speedup vs baseline: 2.2821x; 1.3547x over previous
#include <cuda_runtime.h>
#include <stdint.h>

// FloodPath: 16-step binary flood fill, bit-packed, L2-resident planes.
// R10: pack -> 8 launches of a 2-step-fused CA kernel (1-row halo pyramid,
// redundant compute) -> unpack (shfl-broadcast, 16-plane count ripple).

#define HW    4096
#define WPR   128                 // 32-bit words per row
#define NWORD (HW * WPR)          // 524288 words = 2 MB per plane
#define STEPS 16

__device__ uint32_t g_free[NWORD];              // bit=1: cell is free
__device__ uint32_t g_plane[STEPS + 1][NWORD];  // flood after step t

// ---- pack: warp ballots 32 cells -> 1 word. Coalesced 256B loads.
__global__ void __launch_bounds__(256)
pack_kernel(const float2* __restrict__ in)
{
    const int warp = (blockIdx.x * 256 + threadIdx.x) >> 5;
    const int lane = threadIdx.x & 31;
    const int w0   = warp * 32;
#pragma unroll 4
    for (int i = 0; i < 32; i++) {
        int w = w0 + i;
        float2 v = in[(size_t)w * 32 + lane];
        uint32_t fr = __ballot_sync(0xffffffffu, v.x == 0.f);
        uint32_t fl = __ballot_sync(0xffffffffu, v.y != 0.f);
        if (lane == 0) { g_free[w] = fr; g_plane[0][w] = fl; }
    }
}

// one CA step for a uint4 row segment (lane = 4 words of a 4096-bit row)
__device__ __forceinline__ uint4
castep(const uint4 up, const uint4 s, const uint4 dn, const uint4 fr, int lane)
{
    uint32_t lf = __shfl_up_sync(0xffffffffu, s.w, 1);
    uint32_t rt = __shfl_down_sync(0xffffffffu, s.x, 1);
    if (lane == 0)  lf = 0u;
    if (lane == 31) rt = 0u;
    uint4 o;
    o.x = (s.x | up.x | dn.x | __funnelshift_l(lf,  s.x, 1)
                             | __funnelshift_r(s.x, s.y, 1)) & fr.x;
    o.y = (s.y | up.y | dn.y | __funnelshift_l(s.x, s.y, 1)
                             | __funnelshift_r(s.y, s.z, 1)) & fr.y;
    o.z = (s.z | up.z | dn.z | __funnelshift_l(s.y, s.z, 1)
                             | __funnelshift_r(s.z, s.w, 1)) & fr.z;
    o.w = (s.w | up.w | dn.w | __funnelshift_l(s.z, s.w, 1)
                             | __funnelshift_r(s.w, rt,  1)) & fr.w;
    return o;
}

// ---- 2 fused steps: reads plane t-1, writes planes t and t+1.
// Pyramid: step-A on rows y-1,y,y+1 (redundant), step-B on row y.
__global__ void __launch_bounds__(512)
fstep_kernel(int t)
{
    const uint32_t* __restrict__ src = g_plane[t - 1];
    uint32_t*       __restrict__ dA  = g_plane[t];
    uint32_t*       __restrict__ dB  = g_plane[t + 1];

    const int g    = blockIdx.x * 512 + threadIdx.x;  // uint4 group id
    const int y    = g >> 5;                          // row
    const int lane = threadIdx.x & 31;
    const int b    = g * 4;

    const uint4 z = make_uint4(0u, 0u, 0u, 0u);
    const uint4 sm2 = (y > 1)      ? *(const uint4*)(src + b - 2 * WPR) : z;
    const uint4 sm1 = (y > 0)      ? *(const uint4*)(src + b - WPR)     : z;
    const uint4 s0  =                *(const uint4*)(src + b);
    const uint4 sp1 = (y < HW - 1) ? *(const uint4*)(src + b + WPR)     : z;
    const uint4 sp2 = (y < HW - 2) ? *(const uint4*)(src + b + 2 * WPR) : z;
    const uint4 fm1 = (y > 0)      ? *(const uint4*)(g_free + b - WPR)  : z;
    const uint4 f0  =                *(const uint4*)(g_free + b);
    const uint4 fp1 = (y < HW - 1) ? *(const uint4*)(g_free + b + WPR)  : z;

    // step A (produces plane t) on rows y-1, y, y+1
    const uint4 a_m1 = castep(sm2, sm1, s0,  fm1, lane);
    const uint4 a_0  = castep(sm1, s0,  sp1, f0,  lane);
    const uint4 a_p1 = castep(s0,  sp1, sp2, fp1, lane);
    *(uint4*)(dA + b) = a_0;

    // step B (produces plane t+1) on row y
    const uint4 b_0 = castep(a_m1, a_0, a_p1, f0, lane);
    *(uint4*)(dB + b) = b_0;
}

// ---- unpack: lane owns word w0+lane (coalesced loads, 16-plane count
// ripple), shfl-broadcast each word's 7 values; coalesced 384B span/word.
__global__ void __launch_bounds__(256)
unpack_kernel(float* __restrict__ out)
{
    const int w    = blockIdx.x * 256 + threadIdx.x;
    const int lane = threadIdx.x & 31;
    const int w0   = w - lane;

    const uint32_t fr = g_free[w];
    const uint32_t fw = g_plane[STEPS][w];

    uint32_t c0 = 0u, c1 = 0u, c2 = 0u, c3 = 0u, c4 = 0u;
#pragma unroll
    for (int t = 1; t <= STEPS; t++) {
        uint32_t carry = g_plane[t][w], x;
        x = c0 & carry; c0 ^= carry; carry = x;
        x = c1 & carry; c1 ^= carry; carry = x;
        x = c2 & carry; c2 ^= carry; carry = x;
        x = c3 & carry; c3 ^= carry; carry = x;
        c4 ^= carry;
    }

#pragma unroll
    for (int k = 0; k < 32; k++) {
        const uint32_t bfr = __shfl_sync(0xffffffffu, fr, k);
        const uint32_t bfw = __shfl_sync(0xffffffffu, fw, k);
        const uint32_t b0  = __shfl_sync(0xffffffffu, c0, k);
        const uint32_t b1  = __shfl_sync(0xffffffffu, c1, k);
        const uint32_t b2  = __shfl_sync(0xffffffffu, c2, k);
        const uint32_t b3  = __shfl_sync(0xffffffffu, c3, k);
        const uint32_t b4  = __shfl_sync(0xffffffffu, c4, k);

        const float occ = (float)(((bfr >> lane) & 1u) ^ 1u);
        const float fld = (float)((bfw >> lane) & 1u);
        const uint32_t c =  ((b0 >> lane) & 1u)
                         | (((b1 >> lane) & 1u) << 1)
                         | (((b2 >> lane) & 1u) << 2)
                         | (((b3 >> lane) & 1u) << 3)
                         | (((b4 >> lane) & 1u) << 4);

        float* o = out + (size_t)(w0 + k) * 96 + lane * 3;
        o[0] = occ;
        o[1] = fld;
        o[2] = (float)c;
    }
}

extern "C" void kernel_launch(void* const* d_in, const int* in_sizes, int n_in,
                              void* d_out, int out_size)
{
    const float2* in  = (const float2*)d_in[0];  // flood_input [H,W,2] f32
    float*        out = (float*)d_out;           // [H,W,3] f32
    (void)in_sizes; (void)n_in; (void)out_size;

    pack_kernel<<<2048, 256>>>(in);
    for (int t = 1; t <= STEPS; t += 2)
        fstep_kernel<<<256, 512>>>(t);           // 2 steps per launch
    unpack_kernel<<<2048, 256>>>(out);
}